// round 3
// baseline (speedup 1.0000x reference)
#include <cuda_runtime.h>
#include <cstdint>
#include <math.h>

#define NTOK 8192
#define DDIM 1024
#define FDIM 1024
#define NEXP 8
#define NGRP 9
#define MAT  (DDIM * FDIM)

// ---------------- scratch (device globals; no runtime allocation) ----------
__device__ float g_wgT[NEXP * MAT];      // [e][f][d]  K-major gate weights
__device__ float g_wuT[NEXP * MAT];      // [e][f][d]
__device__ float g_wdT[NEXP * MAT];      // [e][d][f]
__device__ float g_sgT[MAT];
__device__ float g_suT[MAT];
__device__ float g_sdT[MAT];
__device__ float g_x32[NTOK * DDIM];     // tf32-rounded activations
__device__ float g_h [NGRP * NTOK * FDIM]; // SwiGLU hidden per group
__device__ float g_eo[NGRP * NTOK * DDIM]; // expert outputs per group
__device__ int   g_cnt[NGRP];
__device__ int   g_tok[NEXP * NTOK];
__device__ int   g_slot_e[NTOK * 2];
__device__ int   g_slot_p[NTOK * 2];
__device__ float g_slot_w[NTOK * 2];

// ---------------- helpers ---------------------------------------------------
__device__ __forceinline__ uint32_t s2u(const void* p) {
    uint32_t a;
    asm("{ .reg .u64 t; cvta.to.shared.u64 t, %1; cvt.u32.u64 %0, t; }"
        : "=r"(a) : "l"(p));
    return a;
}

__device__ __forceinline__ float rna_f(float x) {  // round f32 -> tf32 value
    uint32_t u;
    asm("cvt.rna.tf32.f32 %0, %1;" : "=r"(u) : "f"(x));
    return __uint_as_float(u);
}

__device__ __forceinline__ void cp16(uint32_t dst, const float* src) {
    asm volatile("cp.async.cg.shared.global [%0], [%1], 16;"
                 :: "r"(dst), "l"(src) : "memory");
}
#define CP_COMMIT() asm volatile("cp.async.commit_group;" ::: "memory")
#define CP_WAIT0()  asm volatile("cp.async.wait_group 0;" ::: "memory")
#define CP_WAIT1()  asm volatile("cp.async.wait_group 1;" ::: "memory")

// m16n8k8 tf32 mma, fp32 accumulate (arch-agnostic PTX; works on sm_100)
#define MMA8(c, a, b0, b1)                                                  \
    asm volatile("mma.sync.aligned.m16n8k8.row.col.f32.tf32.tf32.f32 "      \
                 "{%0,%1,%2,%3}, {%4,%5,%6,%7}, {%8,%9}, {%0,%1,%2,%3};"    \
                 : "+f"((c)[0]), "+f"((c)[1]), "+f"((c)[2]), "+f"((c)[3])   \
                 : "r"((a)[0]), "r"((a)[1]), "r"((a)[2]), "r"((a)[3]),      \
                   "r"(b0), "r"(b1))

#define ASTR 36          // smem row stride in floats (16B aligned, conflict-free)

// ---------------- small kernels ---------------------------------------------
__global__ void k_prep() {
    int i = threadIdx.x;
    if (i < NEXP) g_cnt[i] = 0;
    if (i == NEXP) g_cnt[NEXP] = NTOK;
}

__global__ void k_roundx(const float* __restrict__ x) {
    int i = blockIdx.x * blockDim.x + threadIdx.x;
    float4 v = reinterpret_cast<const float4*>(x)[i];
    v.x = rna_f(v.x); v.y = rna_f(v.y); v.z = rna_f(v.z); v.w = rna_f(v.w);
    reinterpret_cast<float4*>(g_x32)[i] = v;
}

__global__ void k_transpose(const float* __restrict__ wg, const float* __restrict__ wu,
                            const float* __restrict__ wd, const float* __restrict__ sg,
                            const float* __restrict__ su, const float* __restrict__ sd) {
    __shared__ float t[32][33];
    int z = blockIdx.z;
    const float* src; float* dst;
    if (z < 8)       { src = wg + (size_t)z * MAT;        dst = g_wgT + (size_t)z * MAT; }
    else if (z < 16) { src = wu + (size_t)(z - 8) * MAT;  dst = g_wuT + (size_t)(z - 8) * MAT; }
    else if (z < 24) { src = wd + (size_t)(z - 16) * MAT; dst = g_wdT + (size_t)(z - 16) * MAT; }
    else if (z == 24){ src = sg; dst = g_sgT; }
    else if (z == 25){ src = su; dst = g_suT; }
    else             { src = sd; dst = g_sdT; }
    int bx = blockIdx.x * 32, by = blockIdx.y * 32;
    int tx = threadIdx.x, ty = threadIdx.y;
    #pragma unroll
    for (int i = 0; i < 32; i += 8)
        t[ty + i][tx] = src[(size_t)(by + ty + i) * 1024 + bx + tx];
    __syncthreads();
    #pragma unroll
    for (int i = 0; i < 32; i += 8)
        dst[(size_t)(bx + ty + i) * 1024 + by + tx] = rna_f(t[tx][ty + i]);
}

__global__ void k_router(const float* __restrict__ x, const float* __restrict__ rw) {
    int t = (blockIdx.x * blockDim.x + threadIdx.x) >> 5;
    int lid = threadIdx.x & 31;
    if (t >= NTOK) return;
    const float* xr = x + (size_t)t * DDIM;
    float acc[NEXP];
    #pragma unroll
    for (int e = 0; e < NEXP; e++) acc[e] = 0.f;
    for (int d = lid; d < DDIM; d += 32) {
        float xv = xr[d];
        const float* w = rw + d * NEXP;
        #pragma unroll
        for (int e = 0; e < NEXP; e++) acc[e] += xv * w[e];
    }
    #pragma unroll
    for (int e = 0; e < NEXP; e++) {
        #pragma unroll
        for (int off = 16; off > 0; off >>= 1)
            acc[e] += __shfl_xor_sync(0xffffffffu, acc[e], off);
    }
    if (lid == 0) {
        float mx = acc[0];
        #pragma unroll
        for (int e = 1; e < NEXP; e++) mx = fmaxf(mx, acc[e]);
        float p[NEXP], s = 0.f;
        #pragma unroll
        for (int e = 0; e < NEXP; e++) { p[e] = expf(acc[e] - mx); s += p[e]; }
        #pragma unroll
        for (int e = 0; e < NEXP; e++) p[e] /= s;
        int i0 = 0;
        #pragma unroll
        for (int e = 1; e < NEXP; e++) if (p[e] > p[i0]) i0 = e;
        int i1 = (i0 == 0) ? 1 : 0;
        #pragma unroll
        for (int e = 0; e < NEXP; e++) if (e != i0 && p[e] > p[i1]) i1 = e;
        float den = p[i0] + p[i1] + 1e-9f;
        float w0 = p[i0] / den, w1 = p[i1] / den;
        int p0 = atomicAdd(&g_cnt[i0], 1);
        int p1 = atomicAdd(&g_cnt[i1], 1);
        g_tok[i0 * NTOK + p0] = t;
        g_tok[i1 * NTOK + p1] = t;
        g_slot_e[2 * t] = i0;  g_slot_p[2 * t] = p0;  g_slot_w[2 * t] = w0;
        g_slot_e[2 * t + 1] = i1; g_slot_p[2 * t + 1] = p1; g_slot_w[2 * t + 1] = w1;
    }
}

// ---------------- GEMM1: h = silu(A@Wg) * (A@Wu), dual accumulator ----------
// CTA: 256 thr, tile M=128 x N=64 (both gate & up). 2-stage cp.async pipeline.
// smem per stage: A 128x36, Bg 64x36, Bu 64x36 floats. Stage size 9216 floats.
__global__ void __launch_bounds__(256, 2) k_gemm1() {
    int g = blockIdx.z, mt = blockIdx.y, nt = blockIdx.x;
    int cnt = g_cnt[g];
    if (mt * 128 >= cnt) return;

    extern __shared__ float sm[];
    uint32_t sb = s2u(sm);
    int tid = threadIdx.x, lane = tid & 31, wid = tid >> 5;
    int wm = wid >> 1, wn = wid & 1;        // warp grid 4 x 2
    int lq = lane >> 2, lr = lane & 3;
    int trow = tid >> 3, tcol = (tid & 7) * 4;

    // global source pointers for this thread's cp.async chunks
    const float* aptr[4];
    #pragma unroll
    for (int i = 0; i < 4; i++) {
        int r = mt * 128 + trow + i * 32;
        int row;
        if (g < NEXP) row = g_tok[g * NTOK + (r < cnt ? r : cnt - 1)];
        else          row = r;
        aptr[i] = g_x32 + (size_t)row * DDIM + tcol;
    }
    const float* gbase = (g < NEXP) ? g_wgT + (size_t)g * MAT : g_sgT;
    const float* ubase = (g < NEXP) ? g_wuT + (size_t)g * MAT : g_suT;
    const float* gptr[2]; const float* uptr[2];
    #pragma unroll
    for (int i = 0; i < 2; i++) {
        int r = nt * 64 + trow + i * 32;
        gptr[i] = gbase + (size_t)r * DDIM + tcol;
        uptr[i] = ubase + (size_t)r * DDIM + tcol;
    }
    uint32_t dstA[4], dstG[2], dstU[2];
    #pragma unroll
    for (int i = 0; i < 4; i++) dstA[i] = ((trow + i * 32) * ASTR + tcol) * 4;
    #pragma unroll
    for (int i = 0; i < 2; i++) {
        dstG[i] = (4608 + (trow + i * 32) * ASTR + tcol) * 4;
        dstU[i] = (6912 + (trow + i * 32) * ASTR + tcol) * 4;
    }

    auto load_stage = [&](int s, int c) {
        uint32_t base = sb + s * 36864u;
        int k0 = c * 32;
        #pragma unroll
        for (int i = 0; i < 4; i++) cp16(base + dstA[i], aptr[i] + k0);
        #pragma unroll
        for (int i = 0; i < 2; i++) {
            cp16(base + dstG[i], gptr[i] + k0);
            cp16(base + dstU[i], uptr[i] + k0);
        }
    };

    float ag[2][4][4], au[2][4][4];
    #pragma unroll
    for (int mi = 0; mi < 2; mi++)
        #pragma unroll
        for (int ni = 0; ni < 4; ni++)
            #pragma unroll
            for (int q = 0; q < 4; q++) { ag[mi][ni][q] = 0.f; au[mi][ni][q] = 0.f; }

    load_stage(0, 0); CP_COMMIT();
    for (int c = 0; c < 32; c++) {
        int s = c & 1;
        if (c + 1 < 32) { load_stage(s ^ 1, c + 1); CP_COMMIT(); CP_WAIT1(); }
        else CP_WAIT0();
        __syncthreads();
        const float* A  = sm + s * 9216 + (wm * 32 + lq) * ASTR;
        const float* Bg = sm + s * 9216 + 4608 + (wn * 32 + lq) * ASTR;
        const float* Bu = sm + s * 9216 + 6912 + (wn * 32 + lq) * ASTR;
        #pragma unroll
        for (int ks = 0; ks < 4; ks++) {
            int kk = ks * 8 + lr;
            uint32_t a[2][4];
            #pragma unroll
            for (int mi = 0; mi < 2; mi++) {
                const float* Ap = A + mi * 16 * ASTR;
                a[mi][0] = __float_as_uint(Ap[kk]);
                a[mi][1] = __float_as_uint(Ap[8 * ASTR + kk]);
                a[mi][2] = __float_as_uint(Ap[kk + 4]);
                a[mi][3] = __float_as_uint(Ap[8 * ASTR + kk + 4]);
            }
            #pragma unroll
            for (int ni = 0; ni < 4; ni++) {
                uint32_t bg0 = __float_as_uint(Bg[ni * 8 * ASTR + kk]);
                uint32_t bg1 = __float_as_uint(Bg[ni * 8 * ASTR + kk + 4]);
                uint32_t bu0 = __float_as_uint(Bu[ni * 8 * ASTR + kk]);
                uint32_t bu1 = __float_as_uint(Bu[ni * 8 * ASTR + kk + 4]);
                #pragma unroll
                for (int mi = 0; mi < 2; mi++) {
                    MMA8(ag[mi][ni], a[mi], bg0, bg1);
                    MMA8(au[mi][ni], a[mi], bu0, bu1);
                }
            }
        }
        __syncthreads();
    }

    // fused SwiGLU epilogue -> g_h (tf32-rounded for GEMM2)
    float* hp = g_h + ((size_t)g * NTOK + mt * 128) * FDIM + nt * 64;
    #pragma unroll
    for (int mi = 0; mi < 2; mi++) {
        #pragma unroll
        for (int ni = 0; ni < 4; ni++) {
            int r0 = wm * 32 + mi * 16 + lq;
            int cc = wn * 32 + ni * 8 + lr * 2;
            float gv, uv, v0, v1;
            gv = ag[mi][ni][0]; uv = au[mi][ni][0];
            v0 = rna_f(gv / (1.f + expf(-gv)) * uv);
            gv = ag[mi][ni][1]; uv = au[mi][ni][1];
            v1 = rna_f(gv / (1.f + expf(-gv)) * uv);
            *reinterpret_cast<float2*>(hp + (size_t)r0 * FDIM + cc) = make_float2(v0, v1);
            gv = ag[mi][ni][2]; uv = au[mi][ni][2];
            v0 = rna_f(gv / (1.f + expf(-gv)) * uv);
            gv = ag[mi][ni][3]; uv = au[mi][ni][3];
            v1 = rna_f(gv / (1.f + expf(-gv)) * uv);
            *reinterpret_cast<float2*>(hp + (size_t)(r0 + 8) * FDIM + cc) = make_float2(v0, v1);
        }
    }
}

// ---------------- GEMM2: eo = h @ Wd -----------------------------------------
// smem per stage: A 128x36 + B 64x36 floats = 6912 floats.
__global__ void __launch_bounds__(256, 2) k_gemm2() {
    int g = blockIdx.z, mt = blockIdx.y, nt = blockIdx.x;
    int cnt = g_cnt[g];
    if (mt * 128 >= cnt) return;

    extern __shared__ float sm[];
    uint32_t sb = s2u(sm);
    int tid = threadIdx.x, lane = tid & 31, wid = tid >> 5;
    int wm = wid >> 1, wn = wid & 1;
    int lq = lane >> 2, lr = lane & 3;
    int trow = tid >> 3, tcol = (tid & 7) * 4;

    const float* aptr[4];
    #pragma unroll
    for (int i = 0; i < 4; i++)
        aptr[i] = g_h + ((size_t)g * NTOK + mt * 128 + trow + i * 32) * FDIM + tcol;
    const float* bbase = (g < NEXP) ? g_wdT + (size_t)g * MAT : g_sdT;
    const float* bptr[2];
    #pragma unroll
    for (int i = 0; i < 2; i++)
        bptr[i] = bbase + (size_t)(nt * 64 + trow + i * 32) * FDIM + tcol;

    uint32_t dstA[4], dstB[2];
    #pragma unroll
    for (int i = 0; i < 4; i++) dstA[i] = ((trow + i * 32) * ASTR + tcol) * 4;
    #pragma unroll
    for (int i = 0; i < 2; i++) dstB[i] = (4608 + (trow + i * 32) * ASTR + tcol) * 4;

    auto load_stage = [&](int s, int c) {
        uint32_t base = sb + s * 27648u;
        int k0 = c * 32;
        #pragma unroll
        for (int i = 0; i < 4; i++) cp16(base + dstA[i], aptr[i] + k0);
        #pragma unroll
        for (int i = 0; i < 2; i++) cp16(base + dstB[i], bptr[i] + k0);
    };

    float ac[2][4][4];
    #pragma unroll
    for (int mi = 0; mi < 2; mi++)
        #pragma unroll
        for (int ni = 0; ni < 4; ni++)
            #pragma unroll
            for (int q = 0; q < 4; q++) ac[mi][ni][q] = 0.f;

    load_stage(0, 0); CP_COMMIT();
    for (int c = 0; c < 32; c++) {
        int s = c & 1;
        if (c + 1 < 32) { load_stage(s ^ 1, c + 1); CP_COMMIT(); CP_WAIT1(); }
        else CP_WAIT0();
        __syncthreads();
        const float* A = sm + s * 6912 + (wm * 32 + lq) * ASTR;
        const float* B = sm + s * 6912 + 4608 + (wn * 32 + lq) * ASTR;
        #pragma unroll
        for (int ks = 0; ks < 4; ks++) {
            int kk = ks * 8 + lr;
            uint32_t a[2][4];
            #pragma unroll
            for (int mi = 0; mi < 2; mi++) {
                const float* Ap = A + mi * 16 * ASTR;
                a[mi][0] = __float_as_uint(Ap[kk]);
                a[mi][1] = __float_as_uint(Ap[8 * ASTR + kk]);
                a[mi][2] = __float_as_uint(Ap[kk + 4]);
                a[mi][3] = __float_as_uint(Ap[8 * ASTR + kk + 4]);
            }
            #pragma unroll
            for (int ni = 0; ni < 4; ni++) {
                uint32_t b0 = __float_as_uint(B[ni * 8 * ASTR + kk]);
                uint32_t b1 = __float_as_uint(B[ni * 8 * ASTR + kk + 4]);
                #pragma unroll
                for (int mi = 0; mi < 2; mi++) MMA8(ac[mi][ni], a[mi], b0, b1);
            }
        }
        __syncthreads();
    }

    float* ep = g_eo + ((size_t)g * NTOK + mt * 128) * DDIM + nt * 64;
    #pragma unroll
    for (int mi = 0; mi < 2; mi++) {
        #pragma unroll
        for (int ni = 0; ni < 4; ni++) {
            int r0 = wm * 32 + mi * 16 + lq;
            int cc = wn * 32 + ni * 8 + lr * 2;
            *reinterpret_cast<float2*>(ep + (size_t)r0 * DDIM + cc) =
                make_float2(ac[mi][ni][0], ac[mi][ni][1]);
            *reinterpret_cast<float2*>(ep + (size_t)(r0 + 8) * DDIM + cc) =
                make_float2(ac[mi][ni][2], ac[mi][ni][3]);
        }
    }
}

// ---------------- combine: out = shared + w0*eo0 + w1*eo1 --------------------
__global__ void k_combine(float* __restrict__ out) {
    int t = blockIdx.x;
    int e0 = g_slot_e[2 * t], e1 = g_slot_e[2 * t + 1];
    int p0 = g_slot_p[2 * t], p1 = g_slot_p[2 * t + 1];
    float w0 = g_slot_w[2 * t], w1 = g_slot_w[2 * t + 1];
    const float4* sh = reinterpret_cast<const float4*>(g_eo + ((size_t)NEXP * NTOK + t) * DDIM);
    const float4* a  = reinterpret_cast<const float4*>(g_eo + ((size_t)e0 * NTOK + p0) * DDIM);
    const float4* b  = reinterpret_cast<const float4*>(g_eo + ((size_t)e1 * NTOK + p1) * DDIM);
    float4* o = reinterpret_cast<float4*>(out + (size_t)t * DDIM);
    int i = threadIdx.x;  // 256 threads * float4 = 1024 floats
    float4 s = sh[i], xa = a[i], xb = b[i];
    o[i] = make_float4(s.x + w0 * xa.x + w1 * xb.x,
                       s.y + w0 * xa.y + w1 * xb.y,
                       s.z + w0 * xa.z + w1 * xb.z,
                       s.w + w0 * xa.w + w1 * xb.w);
}

// ---------------- launch -----------------------------------------------------
extern "C" void kernel_launch(void* const* d_in, const int* in_sizes, int n_in,
                              void* d_out, int out_size) {
    const float* x  = (const float*)d_in[0];
    const float* rw = (const float*)d_in[1];
    const float* sg = (const float*)d_in[2];
    const float* su = (const float*)d_in[3];
    const float* sd = (const float*)d_in[4];
    const float* wg = (const float*)d_in[5];
    const float* wu = (const float*)d_in[6];
    const float* wd = (const float*)d_in[7];
    float* out = (float*)d_out;

    cudaFuncSetAttribute(k_gemm1, cudaFuncAttributeMaxDynamicSharedMemorySize, 73728);
    cudaFuncSetAttribute(k_gemm2, cudaFuncAttributeMaxDynamicSharedMemorySize, 55296);

    k_prep<<<1, 32>>>();
    k_roundx<<<NTOK * DDIM / (256 * 4), 256>>>(x);
    k_transpose<<<dim3(32, 32, 27), dim3(32, 8)>>>(wg, wu, wd, sg, su, sd);
    k_router<<<NTOK / 8, 256>>>(x, rw);
    k_gemm1<<<dim3(16, 64, NGRP), 256, 73728>>>();
    k_gemm2<<<dim3(16, 64, NGRP), 256, 55296>>>();
    k_combine<<<NTOK, 256>>>(out);
}

// round 5
// speedup vs baseline: 1.0577x; 1.0577x over previous
#include <cuda_runtime.h>
#include <cstdint>
#include <math.h>

#define NTOK 8192
#define DDIM 1024
#define FDIM 1024
#define NEXP 8
#define NGRP 9
#define MAT  (DDIM * FDIM)

// ---------------- scratch (device globals; no runtime allocation) ----------
__device__ float g_wg32[NEXP * MAT];   // rna-rounded, original [D][F] layout
__device__ float g_wu32[NEXP * MAT];
__device__ float g_wd32[NEXP * MAT];   // [F][D]
__device__ float g_sg32[MAT];
__device__ float g_su32[MAT];
__device__ float g_sd32[MAT];
__device__ float g_rwT[NEXP * DDIM];   // router weights transposed [E][D]
__device__ float g_x32[NTOK * DDIM];   // tf32-rounded activations
__device__ float g_h [NGRP * NTOK * FDIM];
__device__ float g_eo[NGRP * NTOK * DDIM];
__device__ int   g_cnt[NGRP];
__device__ int   g_tok[NEXP * NTOK];
__device__ int   g_slot_e[NTOK * 2];
__device__ int   g_slot_p[NTOK * 2];
__device__ float g_slot_w[NTOK * 2];

// ---------------- helpers ---------------------------------------------------
__device__ __forceinline__ uint32_t s2u(const void* p) {
    uint32_t a;
    asm("{ .reg .u64 t; cvta.to.shared.u64 t, %1; cvt.u32.u64 %0, t; }"
        : "=r"(a) : "l"(p));
    return a;
}

__device__ __forceinline__ float rna_f(float x) {  // round f32 -> tf32 value
    uint32_t u;
    asm("cvt.rna.tf32.f32 %0, %1;" : "=r"(u) : "f"(x));
    return __uint_as_float(u);
}

__device__ __forceinline__ void cp16(uint32_t dst, const float* src) {
    asm volatile("cp.async.cg.shared.global [%0], [%1], 16;"
                 :: "r"(dst), "l"(src) : "memory");
}
#define CP_COMMIT() asm volatile("cp.async.commit_group;" ::: "memory")
#define CP_WAIT1()  asm volatile("cp.async.wait_group 1;" ::: "memory")

// m16n8k8 tf32 mma, fp32 accumulate
#define MMA8(c, a, b0, b1)                                                  \
    asm volatile("mma.sync.aligned.m16n8k8.row.col.f32.tf32.tf32.f32 "      \
                 "{%0,%1,%2,%3}, {%4,%5,%6,%7}, {%8,%9}, {%0,%1,%2,%3};"    \
                 : "+f"((c)[0]), "+f"((c)[1]), "+f"((c)[2]), "+f"((c)[3])   \
                 : "r"((a)[0]), "r"((a)[1]), "r"((a)[2]), "r"((a)[3]),      \
                   "r"(b0), "r"(b1))

#define ASTR 36     // A smem stride (m-major): banks (4*lq+lr) distinct
#define BSTR1 72    // B smem stride GEMM1 (k-major, 64-wide rows): 72%32==8
#define BSTR2 136   // B smem stride GEMM2 (128-wide rows): 136%32==8

// GEMM1 stage: A 256x36 = 9216 w, Bg 32x72 = 2304 w, Bu 2304 w -> 13824 words
#define G1_STAGE_W 13824
#define G1_BG_OFF  9216
#define G1_BU_OFF  11520
#define G1_SMEM    (3 * G1_STAGE_W * 4)
// GEMM2 stage: A 9216 w, B 32x136 = 4352 w -> 13568 words
#define G2_STAGE_W 13568
#define G2_B_OFF   9216
#define G2_SMEM    (3 * G2_STAGE_W * 4)

// ---------------- small kernels ---------------------------------------------
__global__ void k_prep(const float* __restrict__ rw) {
    int tid = threadIdx.x;
    if (tid < NEXP) g_cnt[tid] = 0;
    if (tid == NEXP) g_cnt[NEXP] = NTOK;
    for (int i = tid; i < NEXP * DDIM; i += blockDim.x) {
        int d = i >> 3, e = i & 7;
        g_rwT[e * DDIM + d] = rw[i];
    }
}

__global__ void k_roundx(const float* __restrict__ x) {
    int i = blockIdx.x * blockDim.x + threadIdx.x;
    float4 v = reinterpret_cast<const float4*>(x)[i];
    v.x = rna_f(v.x); v.y = rna_f(v.y); v.z = rna_f(v.z); v.w = rna_f(v.w);
    reinterpret_cast<float4*>(g_x32)[i] = v;
}

__global__ void k_roundw(const float* __restrict__ wg, const float* __restrict__ wu,
                         const float* __restrict__ wd, const float* __restrict__ sg,
                         const float* __restrict__ su, const float* __restrict__ sd) {
    int z = blockIdx.z;
    const float* src; float* dst;
    if (z < 8)       { src = wg + (size_t)z * MAT;        dst = g_wg32 + (size_t)z * MAT; }
    else if (z < 16) { src = wu + (size_t)(z - 8) * MAT;  dst = g_wu32 + (size_t)(z - 8) * MAT; }
    else if (z < 24) { src = wd + (size_t)(z - 16) * MAT; dst = g_wd32 + (size_t)(z - 16) * MAT; }
    else if (z == 24){ src = sg; dst = g_sg32; }
    else if (z == 25){ src = su; dst = g_su32; }
    else             { src = sd; dst = g_sd32; }
    int i = blockIdx.x * blockDim.x + threadIdx.x;
    float4 v = reinterpret_cast<const float4*>(src)[i];
    v.x = rna_f(v.x); v.y = rna_f(v.y); v.z = rna_f(v.z); v.w = rna_f(v.w);
    reinterpret_cast<float4*>(dst)[i] = v;
}

__global__ void k_router(const float* __restrict__ x) {
    int t = (blockIdx.x * blockDim.x + threadIdx.x) >> 5;
    int lid = threadIdx.x & 31;
    if (t >= NTOK) return;
    const float4* x4 = reinterpret_cast<const float4*>(x + (size_t)t * DDIM);
    float acc[NEXP];
    #pragma unroll
    for (int e = 0; e < NEXP; e++) acc[e] = 0.f;
    #pragma unroll
    for (int it = 0; it < 8; it++) {
        int idx = lid + it * 32;
        float4 xv = x4[idx];
        #pragma unroll
        for (int e = 0; e < NEXP; e++) {
            float4 w = reinterpret_cast<const float4*>(g_rwT + e * DDIM)[idx];
            acc[e] += xv.x * w.x + xv.y * w.y + xv.z * w.z + xv.w * w.w;
        }
    }
    #pragma unroll
    for (int e = 0; e < NEXP; e++) {
        #pragma unroll
        for (int off = 16; off > 0; off >>= 1)
            acc[e] += __shfl_xor_sync(0xffffffffu, acc[e], off);
    }
    if (lid == 0) {
        // top-2 on logits (softmax is monotone -> identical selection/tie rules)
        int i0 = 0;
        #pragma unroll
        for (int e = 1; e < NEXP; e++) if (acc[e] > acc[i0]) i0 = e;
        int i1 = (i0 == 0) ? 1 : 0;
        #pragma unroll
        for (int e = 0; e < NEXP; e++) if (e != i0 && acc[e] > acc[i1]) i1 = e;
        float mx = acc[i0];
        float s = 0.f;
        #pragma unroll
        for (int e = 0; e < NEXP; e++) s += expf(acc[e] - mx);
        float p0 = expf(acc[i0] - mx) / s, p1 = expf(acc[i1] - mx) / s;
        float den = p0 + p1 + 1e-9f;
        float w0 = p0 / den, w1 = p1 / den;
        int q0 = atomicAdd(&g_cnt[i0], 1);
        int q1 = atomicAdd(&g_cnt[i1], 1);
        g_tok[i0 * NTOK + q0] = t;
        g_tok[i1 * NTOK + q1] = t;
        g_slot_e[2 * t] = i0;     g_slot_p[2 * t] = q0;     g_slot_w[2 * t] = w0;
        g_slot_e[2 * t + 1] = i1; g_slot_p[2 * t + 1] = q1; g_slot_w[2 * t + 1] = w1;
    }
}

// ---------------- GEMM1: h = silu(A@Wg) * (A@Wu) -----------------------------
// CTA 256 thr (warps 4M x 2N), tile M=256 N=64 K-chunk=32, warp tile 64x32 dual.
// 3-stage cp.async pipeline, one __syncthreads per chunk.
__global__ void __launch_bounds__(256, 1) k_gemm1() {
    int g = blockIdx.z, mt = blockIdx.y, nt = blockIdx.x;
    int cnt = g_cnt[g];
    if (mt * 256 >= cnt) return;

    extern __shared__ float sm[];
    uint32_t sb = s2u(sm);
    int tid = threadIdx.x, lane = tid & 31, wid = tid >> 5;
    int wm = wid >> 1, wn = wid & 1;
    int lq = lane >> 2, lr = lane & 3;
    int trow = tid >> 3, tcol = (tid & 7) * 4;

    // A source offsets (gathered token rows)
    uint32_t offA[8];
    #pragma unroll
    for (int i = 0; i < 8; i++) {
        int r = mt * 256 + trow + 32 * i;
        int row;
        if (g < NEXP) row = g_tok[g * NTOK + (r < cnt ? r : cnt - 1)];
        else          row = r;
        offA[i] = (uint32_t)row * DDIM + tcol;
    }
    const float* gb = (g < NEXP) ? g_wg32 + (size_t)g * MAT : g_sg32;
    const float* ub = (g < NEXP) ? g_wu32 + (size_t)g * MAT : g_su32;
    int kb0 = tid >> 4, nb0 = (tid & 15) * 4;   // B: idx=tid (+256): kb0(+16), nb0
    uint32_t bcol = (uint32_t)nt * 64 + nb0;

    auto load_stage = [&](int s, int c) {
        uint32_t base = sb + (uint32_t)s * (G1_STAGE_W * 4);
        int k0 = c * 32;
        #pragma unroll
        for (int i = 0; i < 8; i++)
            cp16(base + (uint32_t)((trow + 32 * i) * ASTR + tcol) * 4,
                 g_x32 + offA[i] + k0);
        #pragma unroll
        for (int i = 0; i < 2; i++) {
            int kb = kb0 + 16 * i;
            uint32_t d = (uint32_t)(kb * BSTR1 + nb0) * 4;
            const float* srcg = gb + (size_t)(k0 + kb) * FDIM + bcol;
            const float* srcu = ub + (size_t)(k0 + kb) * FDIM + bcol;
            cp16(base + G1_BG_OFF * 4 + d, srcg);
            cp16(base + G1_BU_OFF * 4 + d, srcu);
        }
    };

    float ag[4][4][4], au[4][4][4];
    #pragma unroll
    for (int mi = 0; mi < 4; mi++)
        #pragma unroll
        for (int ni = 0; ni < 4; ni++)
            #pragma unroll
            for (int q = 0; q < 4; q++) { ag[mi][ni][q] = 0.f; au[mi][ni][q] = 0.f; }

    load_stage(0, 0); CP_COMMIT();
    load_stage(1, 1); CP_COMMIT();
    for (int c = 0; c < 32; c++) {
        CP_WAIT1();
        __syncthreads();
        if (c + 2 < 32) load_stage((c + 2) % 3, c + 2);
        CP_COMMIT();
        const float* As  = sm + (c % 3) * G1_STAGE_W;
        const float* Bgs = As + G1_BG_OFF;
        const float* Bus = As + G1_BU_OFF;
        #pragma unroll
        for (int ks = 0; ks < 4; ks++) {
            int kk = ks * 8 + lr;
            uint32_t a[4][4];
            #pragma unroll
            for (int mi = 0; mi < 4; mi++) {
                int rb = (wm * 64 + mi * 16 + lq) * ASTR;
                a[mi][0] = __float_as_uint(As[rb + kk]);
                a[mi][1] = __float_as_uint(As[rb + 8 * ASTR + kk]);
                a[mi][2] = __float_as_uint(As[rb + kk + 4]);
                a[mi][3] = __float_as_uint(As[rb + 8 * ASTR + kk + 4]);
            }
            #pragma unroll
            for (int ni = 0; ni < 4; ni++) {
                int nn = wn * 32 + ni * 8 + lq;
                uint32_t bg0 = __float_as_uint(Bgs[kk * BSTR1 + nn]);
                uint32_t bg1 = __float_as_uint(Bgs[(kk + 4) * BSTR1 + nn]);
                uint32_t bu0 = __float_as_uint(Bus[kk * BSTR1 + nn]);
                uint32_t bu1 = __float_as_uint(Bus[(kk + 4) * BSTR1 + nn]);
                #pragma unroll
                for (int mi = 0; mi < 4; mi++) {
                    MMA8(ag[mi][ni], a[mi], bg0, bg1);
                    MMA8(au[mi][ni], a[mi], bu0, bu1);
                }
            }
        }
    }

    // fused SwiGLU epilogue -> g_h (tf32-rounded for GEMM2)
    float* hp = g_h + ((size_t)g * NTOK + mt * 256) * FDIM + nt * 64;
    #pragma unroll
    for (int mi = 0; mi < 4; mi++) {
        int r0 = wm * 64 + mi * 16 + lq;
        #pragma unroll
        for (int ni = 0; ni < 4; ni++) {
            int cc = wn * 32 + ni * 8 + lr * 2;
            float gv, uv, v0, v1;
            gv = ag[mi][ni][0]; uv = au[mi][ni][0];
            v0 = rna_f(gv / (1.f + __expf(-gv)) * uv);
            gv = ag[mi][ni][1]; uv = au[mi][ni][1];
            v1 = rna_f(gv / (1.f + __expf(-gv)) * uv);
            *reinterpret_cast<float2*>(hp + (size_t)r0 * FDIM + cc) = make_float2(v0, v1);
            gv = ag[mi][ni][2]; uv = au[mi][ni][2];
            v0 = rna_f(gv / (1.f + __expf(-gv)) * uv);
            gv = ag[mi][ni][3]; uv = au[mi][ni][3];
            v1 = rna_f(gv / (1.f + __expf(-gv)) * uv);
            *reinterpret_cast<float2*>(hp + (size_t)(r0 + 8) * FDIM + cc) = make_float2(v0, v1);
        }
    }
}

// ---------------- GEMM2: eo = h @ Wd ------------------------------------------
// CTA 256 thr (4M x 2N), tile M=256 N=128, warp tile 64x64.
__global__ void __launch_bounds__(256, 1) k_gemm2() {
    int g = blockIdx.z, mt = blockIdx.y, nt = blockIdx.x;
    int cnt = g_cnt[g];
    if (mt * 256 >= cnt) return;

    extern __shared__ float sm[];
    uint32_t sb = s2u(sm);
    int tid = threadIdx.x, lane = tid & 31, wid = tid >> 5;
    int wm = wid >> 1, wn = wid & 1;
    int lq = lane >> 2, lr = lane & 3;
    int trow = tid >> 3, tcol = (tid & 7) * 4;

    const float* abase = g_h + ((size_t)g * NTOK + mt * 256) * FDIM;
    const float* bbase = (g < NEXP) ? g_wd32 + (size_t)g * MAT : g_sd32;
    int kb0 = tid >> 5, nb0 = (tid & 31) * 4;   // B: idx=tid+256i -> kb0+8i, nb0
    uint32_t bcol = (uint32_t)nt * 128 + nb0;

    auto load_stage = [&](int s, int c) {
        uint32_t base = sb + (uint32_t)s * (G2_STAGE_W * 4);
        int k0 = c * 32;
        #pragma unroll
        for (int i = 0; i < 8; i++) {
            int r = trow + 32 * i;
            cp16(base + (uint32_t)(r * ASTR + tcol) * 4,
                 abase + (size_t)r * FDIM + k0 + tcol);
        }
        #pragma unroll
        for (int i = 0; i < 4; i++) {
            int kb = kb0 + 8 * i;
            cp16(base + G2_B_OFF * 4 + (uint32_t)(kb * BSTR2 + nb0) * 4,
                 bbase + (size_t)(k0 + kb) * DDIM + bcol);
        }
    };

    float ac[4][8][4];
    #pragma unroll
    for (int mi = 0; mi < 4; mi++)
        #pragma unroll
        for (int ni = 0; ni < 8; ni++)
            #pragma unroll
            for (int q = 0; q < 4; q++) ac[mi][ni][q] = 0.f;

    load_stage(0, 0); CP_COMMIT();
    load_stage(1, 1); CP_COMMIT();
    for (int c = 0; c < 32; c++) {
        CP_WAIT1();
        __syncthreads();
        if (c + 2 < 32) load_stage((c + 2) % 3, c + 2);
        CP_COMMIT();
        const float* As = sm + (c % 3) * G2_STAGE_W;
        const float* Bs = As + G2_B_OFF;
        #pragma unroll
        for (int ks = 0; ks < 4; ks++) {
            int kk = ks * 8 + lr;
            uint32_t a[4][4];
            #pragma unroll
            for (int mi = 0; mi < 4; mi++) {
                int rb = (wm * 64 + mi * 16 + lq) * ASTR;
                a[mi][0] = __float_as_uint(As[rb + kk]);
                a[mi][1] = __float_as_uint(As[rb + 8 * ASTR + kk]);
                a[mi][2] = __float_as_uint(As[rb + kk + 4]);
                a[mi][3] = __float_as_uint(As[rb + 8 * ASTR + kk + 4]);
            }
            #pragma unroll
            for (int ni = 0; ni < 8; ni++) {
                int nn = wn * 64 + ni * 8 + lq;
                uint32_t b0 = __float_as_uint(Bs[kk * BSTR2 + nn]);
                uint32_t b1 = __float_as_uint(Bs[(kk + 4) * BSTR2 + nn]);
                #pragma unroll
                for (int mi = 0; mi < 4; mi++) MMA8(ac[mi][ni], a[mi], b0, b1);
            }
        }
    }

    float* ep = g_eo + ((size_t)g * NTOK + mt * 256) * DDIM + nt * 128;
    #pragma unroll
    for (int mi = 0; mi < 4; mi++) {
        int r0 = wm * 64 + mi * 16 + lq;
        #pragma unroll
        for (int ni = 0; ni < 8; ni++) {
            int cc = wn * 64 + ni * 8 + lr * 2;
            *reinterpret_cast<float2*>(ep + (size_t)r0 * DDIM + cc) =
                make_float2(ac[mi][ni][0], ac[mi][ni][1]);
            *reinterpret_cast<float2*>(ep + (size_t)(r0 + 8) * DDIM + cc) =
                make_float2(ac[mi][ni][2], ac[mi][ni][3]);
        }
    }
}

// ---------------- combine: out = shared + w0*eo0 + w1*eo1 --------------------
__global__ void k_combine(float* __restrict__ out) {
    int t = blockIdx.x;
    int e0 = g_slot_e[2 * t], e1 = g_slot_e[2 * t + 1];
    int p0 = g_slot_p[2 * t], p1 = g_slot_p[2 * t + 1];
    float w0 = g_slot_w[2 * t], w1 = g_slot_w[2 * t + 1];
    const float4* sh = reinterpret_cast<const float4*>(g_eo + ((size_t)NEXP * NTOK + t) * DDIM);
    const float4* a  = reinterpret_cast<const float4*>(g_eo + ((size_t)e0 * NTOK + p0) * DDIM);
    const float4* b  = reinterpret_cast<const float4*>(g_eo + ((size_t)e1 * NTOK + p1) * DDIM);
    float4* o = reinterpret_cast<float4*>(out + (size_t)t * DDIM);
    int i = threadIdx.x;
    float4 s = sh[i], xa = a[i], xb = b[i];
    o[i] = make_float4(s.x + w0 * xa.x + w1 * xb.x,
                       s.y + w0 * xa.y + w1 * xb.y,
                       s.z + w0 * xa.z + w1 * xb.z,
                       s.w + w0 * xa.w + w1 * xb.w);
}

// ---------------- launch -----------------------------------------------------
extern "C" void kernel_launch(void* const* d_in, const int* in_sizes, int n_in,
                              void* d_out, int out_size) {
    const float* x  = (const float*)d_in[0];
    const float* rw = (const float*)d_in[1];
    const float* sg = (const float*)d_in[2];
    const float* su = (const float*)d_in[3];
    const float* sd = (const float*)d_in[4];
    const float* wg = (const float*)d_in[5];
    const float* wu = (const float*)d_in[6];
    const float* wd = (const float*)d_in[7];
    float* out = (float*)d_out;

    cudaFuncSetAttribute(k_gemm1, cudaFuncAttributeMaxDynamicSharedMemorySize, G1_SMEM);
    cudaFuncSetAttribute(k_gemm2, cudaFuncAttributeMaxDynamicSharedMemorySize, G2_SMEM);

    k_prep<<<1, 256>>>(rw);
    k_roundx<<<NTOK * DDIM / (256 * 4), 256>>>(x);
    k_roundw<<<dim3(MAT / (256 * 4), 1, 27), 256>>>(wg, wu, wd, sg, su, sd);
    k_router<<<NTOK / 8, 256>>>(x);
    k_gemm1<<<dim3(16, 32, NGRP), 256, G1_SMEM>>>();
    k_gemm2<<<dim3(8, 32, NGRP), 256, G2_SMEM>>>();
    k_combine<<<NTOK, 256>>>(out);
}

// round 6
// speedup vs baseline: 1.7775x; 1.6805x over previous
#include <cuda_runtime.h>
#include <cuda_fp16.h>
#include <cstdint>
#include <math.h>

#define NTOK 8192
#define DDIM 1024
#define FDIM 1024
#define NEXP 8
#define NGRP 9
#define MAT  (DDIM * FDIM)

// ---------------- scratch (device globals; no runtime allocation) ----------
__device__ __half g_wgT16[NEXP * MAT];   // [e][f][d]  (B^T for GEMM1 gate)
__device__ __half g_wuT16[NEXP * MAT];   // [e][f][d]
__device__ __half g_wdT16[NEXP * MAT];   // [e][d][f]  (B^T for GEMM2)
__device__ __half g_sgT16[MAT];
__device__ __half g_suT16[MAT];
__device__ __half g_sdT16[MAT];
__device__ float  g_rwT[NEXP * DDIM];    // router weights transposed [E][D]
__device__ __half g_x16[NTOK * DDIM];    // fp16 activations
__device__ __half g_h16[(size_t)NGRP * NTOK * FDIM];
__device__ float  g_eo[(size_t)NGRP * NTOK * DDIM];
__device__ int    g_cnt[NGRP];
__device__ int    g_tok[NEXP * NTOK];
__device__ int    g_slot_e[NTOK * 2];
__device__ int    g_slot_p[NTOK * 2];
__device__ float  g_slot_w[NTOK * 2];

// ---------------- helpers ---------------------------------------------------
__device__ __forceinline__ uint32_t s2u(const void* p) {
    uint32_t a;
    asm("{ .reg .u64 t; cvta.to.shared.u64 t, %1; cvt.u32.u64 %0, t; }"
        : "=r"(a) : "l"(p));
    return a;
}

__device__ __forceinline__ void cp16(uint32_t dst, const void* src) {
    asm volatile("cp.async.cg.shared.global [%0], [%1], 16;"
                 :: "r"(dst), "l"(src) : "memory");
}
#define CP_COMMIT() asm volatile("cp.async.commit_group;" ::: "memory")
#define CP_WAIT1()  asm volatile("cp.async.wait_group 1;" ::: "memory")

// m16n8k16 fp16 mma, fp32 accumulate (arch-agnostic; sm_80+)
#define MMA16(c, a, b0, b1)                                                  \
    asm volatile("mma.sync.aligned.m16n8k16.row.col.f32.f16.f16.f32 "        \
                 "{%0,%1,%2,%3}, {%4,%5,%6,%7}, {%8,%9}, {%0,%1,%2,%3};"     \
                 : "+f"((c)[0]), "+f"((c)[1]), "+f"((c)[2]), "+f"((c)[3])    \
                 : "r"((a)[0]), "r"((a)[1]), "r"((a)[2]), "r"((a)[3]),       \
                   "r"(b0), "r"(b1))

#define STRH 72          // smem row stride in halves: 144 B, bank step 4 -> conflict-free
#define KC   64          // K elements per chunk
#define NCHUNK (DDIM / KC)

// GEMM1 stage (halves): A 256x72 = 18432, Bg 64x72 = 4608, Bu 4608 -> 27648
#define G1_STAGE_H 27648
#define G1_BG_OFF  18432
#define G1_BU_OFF  23040
#define G1_SMEM    (3 * G1_STAGE_H * 2)
// GEMM2 stage (halves): A 18432, B 128x72 = 9216 -> 27648
#define G2_STAGE_H 27648
#define G2_B_OFF   18432
#define G2_SMEM    (3 * G2_STAGE_H * 2)

__device__ __forceinline__ uint32_t ldh2(const __half* p) {
    return *reinterpret_cast<const uint32_t*>(p);
}

// ---------------- small kernels ---------------------------------------------
__global__ void k_prep(const float* __restrict__ rw) {
    int tid = threadIdx.x;
    if (tid < NEXP) g_cnt[tid] = 0;
    if (tid == NEXP) g_cnt[NEXP] = NTOK;
    for (int i = tid; i < NEXP * DDIM; i += blockDim.x) {
        int d = i >> 3, e = i & 7;
        g_rwT[e * DDIM + d] = rw[i];
    }
}

__global__ void k_halfx(const float* __restrict__ x) {
    int i = blockIdx.x * blockDim.x + threadIdx.x;
    float4 v = reinterpret_cast<const float4*>(x)[i];
    __half2 h0 = __floats2half2_rn(v.x, v.y);
    __half2 h1 = __floats2half2_rn(v.z, v.w);
    reinterpret_cast<__half2*>(g_x16)[2 * i]     = h0;
    reinterpret_cast<__half2*>(g_x16)[2 * i + 1] = h1;
}

// transpose fp32 [r][c] -> fp16 [c][r] for all 27 weight matrices
__global__ void k_transposeh(const float* __restrict__ wg, const float* __restrict__ wu,
                             const float* __restrict__ wd, const float* __restrict__ sg,
                             const float* __restrict__ su, const float* __restrict__ sd) {
    __shared__ float t[32][33];
    int z = blockIdx.z;
    const float* src; __half* dst;
    if (z < 8)       { src = wg + (size_t)z * MAT;        dst = g_wgT16 + (size_t)z * MAT; }
    else if (z < 16) { src = wu + (size_t)(z - 8) * MAT;  dst = g_wuT16 + (size_t)(z - 8) * MAT; }
    else if (z < 24) { src = wd + (size_t)(z - 16) * MAT; dst = g_wdT16 + (size_t)(z - 16) * MAT; }
    else if (z == 24){ src = sg; dst = g_sgT16; }
    else if (z == 25){ src = su; dst = g_suT16; }
    else             { src = sd; dst = g_sdT16; }
    int bx = blockIdx.x * 32, by = blockIdx.y * 32;
    int tx = threadIdx.x, ty = threadIdx.y;
    #pragma unroll
    for (int i = 0; i < 32; i += 8)
        t[ty + i][tx] = src[(size_t)(by + ty + i) * 1024 + bx + tx];
    __syncthreads();
    #pragma unroll
    for (int i = 0; i < 32; i += 8)
        dst[(size_t)(bx + ty + i) * 1024 + by + tx] = __float2half_rn(t[tx][ty + i]);
}

__global__ void k_router(const float* __restrict__ x) {
    int t = (blockIdx.x * blockDim.x + threadIdx.x) >> 5;
    int lid = threadIdx.x & 31;
    if (t >= NTOK) return;
    const float4* x4 = reinterpret_cast<const float4*>(x + (size_t)t * DDIM);
    float acc[NEXP];
    #pragma unroll
    for (int e = 0; e < NEXP; e++) acc[e] = 0.f;
    #pragma unroll
    for (int it = 0; it < 8; it++) {
        int idx = lid + it * 32;
        float4 xv = x4[idx];
        #pragma unroll
        for (int e = 0; e < NEXP; e++) {
            float4 w = reinterpret_cast<const float4*>(g_rwT + e * DDIM)[idx];
            acc[e] += xv.x * w.x + xv.y * w.y + xv.z * w.z + xv.w * w.w;
        }
    }
    #pragma unroll
    for (int e = 0; e < NEXP; e++) {
        #pragma unroll
        for (int off = 16; off > 0; off >>= 1)
            acc[e] += __shfl_xor_sync(0xffffffffu, acc[e], off);
    }
    if (lid == 0) {
        int i0 = 0;
        #pragma unroll
        for (int e = 1; e < NEXP; e++) if (acc[e] > acc[i0]) i0 = e;
        int i1 = (i0 == 0) ? 1 : 0;
        #pragma unroll
        for (int e = 0; e < NEXP; e++) if (e != i0 && acc[e] > acc[i1]) i1 = e;
        float mx = acc[i0];
        float s = 0.f;
        #pragma unroll
        for (int e = 0; e < NEXP; e++) s += expf(acc[e] - mx);
        float p0 = expf(acc[i0] - mx) / s, p1 = expf(acc[i1] - mx) / s;
        float den = p0 + p1 + 1e-9f;
        float w0 = p0 / den, w1 = p1 / den;
        int q0 = atomicAdd(&g_cnt[i0], 1);
        int q1 = atomicAdd(&g_cnt[i1], 1);
        g_tok[i0 * NTOK + q0] = t;
        g_tok[i1 * NTOK + q1] = t;
        g_slot_e[2 * t] = i0;     g_slot_p[2 * t] = q0;     g_slot_w[2 * t] = w0;
        g_slot_e[2 * t + 1] = i1; g_slot_p[2 * t + 1] = q1; g_slot_w[2 * t + 1] = w1;
    }
}

// ---------------- GEMM1: h = silu(A@Wg) * (A@Wu), fp16 mma -------------------
// CTA 256 thr (4M x 2N warps), tile M=256 N=64, K-chunk 64, warp tile 64x32 dual.
__global__ void __launch_bounds__(256, 1) k_gemm1() {
    int g = blockIdx.z, mt = blockIdx.y, nt = blockIdx.x;
    int cnt = g_cnt[g];
    if (mt * 256 >= cnt) return;

    extern __shared__ __half smh[];
    uint32_t sb = s2u(smh);
    int tid = threadIdx.x, lane = tid & 31, wid = tid >> 5;
    int wm = wid >> 1, wn = wid & 1;
    int lq = lane >> 2, lr = lane & 3;
    int trow = tid >> 3, tcol = (tid & 7) * 8;   // halves

    uint32_t offA[8];
    #pragma unroll
    for (int i = 0; i < 8; i++) {
        int r = mt * 256 + trow + 32 * i;
        int row;
        if (g < NEXP) row = g_tok[g * NTOK + (r < cnt ? r : cnt - 1)];
        else          row = r;
        offA[i] = (uint32_t)row * DDIM + tcol;
    }
    const __half* gb = (g < NEXP) ? g_wgT16 + (size_t)g * MAT : g_sgT16;
    const __half* ub = (g < NEXP) ? g_wuT16 + (size_t)g * MAT : g_suT16;
    uint32_t ncol0 = (uint32_t)nt * 64;

    auto load_stage = [&](int s, int c) {
        uint32_t base = sb + (uint32_t)s * (G1_STAGE_H * 2);
        int k0 = c * KC;
        #pragma unroll
        for (int i = 0; i < 8; i++)
            cp16(base + (uint32_t)((trow + 32 * i) * STRH + tcol) * 2,
                 g_x16 + offA[i] + k0);
        #pragma unroll
        for (int i = 0; i < 2; i++) {
            int r = trow + 32 * i;
            uint32_t d = (uint32_t)(r * STRH + tcol) * 2;
            cp16(base + G1_BG_OFF * 2 + d,
                 gb + (size_t)(ncol0 + r) * DDIM + k0 + tcol);
            cp16(base + G1_BU_OFF * 2 + d,
                 ub + (size_t)(ncol0 + r) * DDIM + k0 + tcol);
        }
    };

    float ag[4][4][4], au[4][4][4];
    #pragma unroll
    for (int mi = 0; mi < 4; mi++)
        #pragma unroll
        for (int ni = 0; ni < 4; ni++)
            #pragma unroll
            for (int q = 0; q < 4; q++) { ag[mi][ni][q] = 0.f; au[mi][ni][q] = 0.f; }

    load_stage(0, 0); CP_COMMIT();
    load_stage(1, 1); CP_COMMIT();
    for (int c = 0; c < NCHUNK; c++) {
        CP_WAIT1();
        __syncthreads();
        if (c + 2 < NCHUNK) load_stage((c + 2) % 3, c + 2);
        CP_COMMIT();
        const __half* As  = smh + (c % 3) * G1_STAGE_H;
        const __half* Bgs = As + G1_BG_OFF;
        const __half* Bus = As + G1_BU_OFF;
        #pragma unroll
        for (int ks = 0; ks < 4; ks++) {
            int kkh = ks * 16 + 2 * lr;
            uint32_t a[4][4];
            #pragma unroll
            for (int mi = 0; mi < 4; mi++) {
                const __half* Ap = As + (wm * 64 + mi * 16 + lq) * STRH + kkh;
                a[mi][0] = ldh2(Ap);
                a[mi][1] = ldh2(Ap + 8 * STRH);
                a[mi][2] = ldh2(Ap + 8);
                a[mi][3] = ldh2(Ap + 8 * STRH + 8);
            }
            #pragma unroll
            for (int ni = 0; ni < 4; ni++) {
                const __half* Bp = Bgs + (wn * 32 + ni * 8 + lq) * STRH + kkh;
                const __half* Up = Bus + (wn * 32 + ni * 8 + lq) * STRH + kkh;
                uint32_t bg0 = ldh2(Bp), bg1 = ldh2(Bp + 8);
                uint32_t bu0 = ldh2(Up), bu1 = ldh2(Up + 8);
                #pragma unroll
                for (int mi = 0; mi < 4; mi++) {
                    MMA16(ag[mi][ni], a[mi], bg0, bg1);
                    MMA16(au[mi][ni], a[mi], bu0, bu1);
                }
            }
        }
    }

    // fused SwiGLU epilogue -> g_h16 (fp16 for GEMM2)
    __half* hp = g_h16 + ((size_t)g * NTOK + mt * 256) * FDIM + nt * 64;
    #pragma unroll
    for (int mi = 0; mi < 4; mi++) {
        int r0 = wm * 64 + mi * 16 + lq;
        #pragma unroll
        for (int ni = 0; ni < 4; ni++) {
            int cc = wn * 32 + ni * 8 + lr * 2;
            float gv, uv, v0, v1;
            gv = ag[mi][ni][0]; uv = au[mi][ni][0];
            v0 = gv / (1.f + __expf(-gv)) * uv;
            gv = ag[mi][ni][1]; uv = au[mi][ni][1];
            v1 = gv / (1.f + __expf(-gv)) * uv;
            *reinterpret_cast<__half2*>(hp + (size_t)r0 * FDIM + cc) = __floats2half2_rn(v0, v1);
            gv = ag[mi][ni][2]; uv = au[mi][ni][2];
            v0 = gv / (1.f + __expf(-gv)) * uv;
            gv = ag[mi][ni][3]; uv = au[mi][ni][3];
            v1 = gv / (1.f + __expf(-gv)) * uv;
            *reinterpret_cast<__half2*>(hp + (size_t)(r0 + 8) * FDIM + cc) = __floats2half2_rn(v0, v1);
        }
    }
}

// ---------------- GEMM2: eo = h @ Wd, fp16 mma --------------------------------
// CTA 256 thr (4M x 2N), tile M=256 N=128, warp tile 64x64.
__global__ void __launch_bounds__(256, 1) k_gemm2() {
    int g = blockIdx.z, mt = blockIdx.y, nt = blockIdx.x;
    int cnt = g_cnt[g];
    if (mt * 256 >= cnt) return;

    extern __shared__ __half smh[];
    uint32_t sb = s2u(smh);
    int tid = threadIdx.x, lane = tid & 31, wid = tid >> 5;
    int wm = wid >> 1, wn = wid & 1;
    int lq = lane >> 2, lr = lane & 3;
    int trow = tid >> 3, tcol = (tid & 7) * 8;

    const __half* abase = g_h16 + ((size_t)g * NTOK + mt * 256) * FDIM;
    const __half* bbase = (g < NEXP) ? g_wdT16 + (size_t)g * MAT : g_sdT16;
    uint32_t ncol0 = (uint32_t)nt * 128;

    auto load_stage = [&](int s, int c) {
        uint32_t base = sb + (uint32_t)s * (G2_STAGE_H * 2);
        int k0 = c * KC;
        #pragma unroll
        for (int i = 0; i < 8; i++) {
            int r = trow + 32 * i;
            cp16(base + (uint32_t)(r * STRH + tcol) * 2,
                 abase + (size_t)r * FDIM + k0 + tcol);
        }
        #pragma unroll
        for (int i = 0; i < 4; i++) {
            int r = trow + 32 * i;
            cp16(base + G2_B_OFF * 2 + (uint32_t)(r * STRH + tcol) * 2,
                 bbase + (size_t)(ncol0 + r) * FDIM + k0 + tcol);
        }
    };

    float ac[4][8][4];
    #pragma unroll
    for (int mi = 0; mi < 4; mi++)
        #pragma unroll
        for (int ni = 0; ni < 8; ni++)
            #pragma unroll
            for (int q = 0; q < 4; q++) ac[mi][ni][q] = 0.f;

    load_stage(0, 0); CP_COMMIT();
    load_stage(1, 1); CP_COMMIT();
    for (int c = 0; c < NCHUNK; c++) {
        CP_WAIT1();
        __syncthreads();
        if (c + 2 < NCHUNK) load_stage((c + 2) % 3, c + 2);
        CP_COMMIT();
        const __half* As = smh + (c % 3) * G2_STAGE_H;
        const __half* Bs = As + G2_B_OFF;
        #pragma unroll
        for (int ks = 0; ks < 4; ks++) {
            int kkh = ks * 16 + 2 * lr;
            uint32_t a[4][4];
            #pragma unroll
            for (int mi = 0; mi < 4; mi++) {
                const __half* Ap = As + (wm * 64 + mi * 16 + lq) * STRH + kkh;
                a[mi][0] = ldh2(Ap);
                a[mi][1] = ldh2(Ap + 8 * STRH);
                a[mi][2] = ldh2(Ap + 8);
                a[mi][3] = ldh2(Ap + 8 * STRH + 8);
            }
            #pragma unroll
            for (int ni = 0; ni < 8; ni++) {
                const __half* Bp = Bs + (wn * 64 + ni * 8 + lq) * STRH + kkh;
                uint32_t b0 = ldh2(Bp), b1 = ldh2(Bp + 8);
                #pragma unroll
                for (int mi = 0; mi < 4; mi++) MMA16(ac[mi][ni], a[mi], b0, b1);
            }
        }
    }

    float* ep = g_eo + ((size_t)g * NTOK + mt * 256) * DDIM + nt * 128;
    #pragma unroll
    for (int mi = 0; mi < 4; mi++) {
        int r0 = wm * 64 + mi * 16 + lq;
        #pragma unroll
        for (int ni = 0; ni < 8; ni++) {
            int cc = wn * 64 + ni * 8 + lr * 2;
            *reinterpret_cast<float2*>(ep + (size_t)r0 * DDIM + cc) =
                make_float2(ac[mi][ni][0], ac[mi][ni][1]);
            *reinterpret_cast<float2*>(ep + (size_t)(r0 + 8) * DDIM + cc) =
                make_float2(ac[mi][ni][2], ac[mi][ni][3]);
        }
    }
}

// ---------------- combine: out = shared + w0*eo0 + w1*eo1 --------------------
__global__ void k_combine(float* __restrict__ out) {
    int t = blockIdx.x;
    int e0 = g_slot_e[2 * t], e1 = g_slot_e[2 * t + 1];
    int p0 = g_slot_p[2 * t], p1 = g_slot_p[2 * t + 1];
    float w0 = g_slot_w[2 * t], w1 = g_slot_w[2 * t + 1];
    const float4* sh = reinterpret_cast<const float4*>(g_eo + ((size_t)NEXP * NTOK + t) * DDIM);
    const float4* a  = reinterpret_cast<const float4*>(g_eo + ((size_t)e0 * NTOK + p0) * DDIM);
    const float4* b  = reinterpret_cast<const float4*>(g_eo + ((size_t)e1 * NTOK + p1) * DDIM);
    float4* o = reinterpret_cast<float4*>(out + (size_t)t * DDIM);
    int i = threadIdx.x;
    float4 s = sh[i], xa = a[i], xb = b[i];
    o[i] = make_float4(s.x + w0 * xa.x + w1 * xb.x,
                       s.y + w0 * xa.y + w1 * xb.y,
                       s.z + w0 * xa.z + w1 * xb.z,
                       s.w + w0 * xa.w + w1 * xb.w);
}

// ---------------- launch -----------------------------------------------------
extern "C" void kernel_launch(void* const* d_in, const int* in_sizes, int n_in,
                              void* d_out, int out_size) {
    const float* x  = (const float*)d_in[0];
    const float* rw = (const float*)d_in[1];
    const float* sg = (const float*)d_in[2];
    const float* su = (const float*)d_in[3];
    const float* sd = (const float*)d_in[4];
    const float* wg = (const float*)d_in[5];
    const float* wu = (const float*)d_in[6];
    const float* wd = (const float*)d_in[7];
    float* out = (float*)d_out;

    cudaFuncSetAttribute(k_gemm1, cudaFuncAttributeMaxDynamicSharedMemorySize, G1_SMEM);
    cudaFuncSetAttribute(k_gemm2, cudaFuncAttributeMaxDynamicSharedMemorySize, G2_SMEM);

    k_prep<<<1, 256>>>(rw);
    k_halfx<<<NTOK * DDIM / (256 * 4), 256>>>(x);
    k_transposeh<<<dim3(32, 32, 27), dim3(32, 8)>>>(wg, wu, wd, sg, su, sd);
    k_router<<<NTOK / 8, 256>>>(x);
    k_gemm1<<<dim3(16, 32, NGRP), 256, G1_SMEM>>>();
    k_gemm2<<<dim3(8, 32, NGRP), 256, G2_SMEM>>>();
    k_combine<<<NTOK, 256>>>(out);
}

// round 7
// speedup vs baseline: 1.8503x; 1.0410x over previous
#include <cuda_runtime.h>
#include <cuda_fp16.h>
#include <cstdint>
#include <math.h>

#define NTOK 8192
#define DDIM 1024
#define FDIM 1024
#define NEXP 8
#define NGRP 9
#define MAT  (DDIM * FDIM)

// ---------------- scratch (device globals; no runtime allocation) ----------
__device__ __half g_wgT16[NEXP * MAT];   // [e][f][d]  (B^T for GEMM1 gate)
__device__ __half g_wuT16[NEXP * MAT];   // [e][f][d]
__device__ __half g_wdT16[NEXP * MAT];   // [e][d][f]  (B^T for GEMM2)
__device__ __half g_sgT16[MAT];
__device__ __half g_suT16[MAT];
__device__ __half g_sdT16[MAT];
__device__ __half g_x16[NTOK * DDIM];    // fp16 activations
__device__ __half g_h16[(size_t)NGRP * NTOK * FDIM];
__device__ __half g_eoh[(size_t)NGRP * NTOK * DDIM];   // expert outputs, fp16
__device__ int    g_cnt[NEXP];
__device__ int    g_tok[NEXP * NTOK];
__device__ int    g_slot_e[NTOK * 2];
__device__ int    g_slot_p[NTOK * 2];
__device__ float  g_slot_w[NTOK * 2];

// ---------------- helpers ---------------------------------------------------
__device__ __forceinline__ uint32_t s2u(const void* p) {
    uint32_t a;
    asm("{ .reg .u64 t; cvta.to.shared.u64 t, %1; cvt.u32.u64 %0, t; }"
        : "=r"(a) : "l"(p));
    return a;
}

__device__ __forceinline__ void cp16(uint32_t dst, const void* src) {
    asm volatile("cp.async.cg.shared.global [%0], [%1], 16;"
                 :: "r"(dst), "l"(src) : "memory");
}
#define CP_COMMIT() asm volatile("cp.async.commit_group;" ::: "memory")
#define CP_WAIT1()  asm volatile("cp.async.wait_group 1;" ::: "memory")

// m16n8k16 fp16 mma, fp32 accumulate (arch-agnostic; sm_80+)
#define MMA16(c, a, b0, b1)                                                  \
    asm volatile("mma.sync.aligned.m16n8k16.row.col.f32.f16.f16.f32 "        \
                 "{%0,%1,%2,%3}, {%4,%5,%6,%7}, {%8,%9}, {%0,%1,%2,%3};"     \
                 : "+f"((c)[0]), "+f"((c)[1]), "+f"((c)[2]), "+f"((c)[3])    \
                 : "r"((a)[0]), "r"((a)[1]), "r"((a)[2]), "r"((a)[3]),       \
                   "r"(b0), "r"(b1))

#define STRH 72          // smem row stride in halves: 144 B, conflict-free
#define KC   64          // K elements per chunk
#define NCHUNK (DDIM / KC)

// GEMM1 stage (halves): A 256x72 = 18432, Bg 64x72 = 4608, Bu 4608 -> 27648
#define G1_STAGE_H 27648
#define G1_BG_OFF  18432
#define G1_BU_OFF  23040
#define G1_SMEM    (3 * G1_STAGE_H * 2)
// GEMM2 stage (halves): A 18432, B 128x72 = 9216 -> 27648
#define G2_STAGE_H 27648
#define G2_B_OFF   18432
#define G2_SMEM    (3 * G2_STAGE_H * 2)

__device__ __forceinline__ uint32_t ldh2(const __half* p) {
    return *reinterpret_cast<const uint32_t*>(p);
}

// ---------------- fused pre-kernel -------------------------------------------
// blocks [0, 1024)          : router (8 tokens/block) + x fp32->fp16 conversion
// blocks [1024, 1024+27648) : weight transpose fp32 [r][c] -> fp16 [c][r]
__global__ void __launch_bounds__(256) k_pre(
    const float* __restrict__ x,  const float* __restrict__ rw,
    const float* __restrict__ wg, const float* __restrict__ wu,
    const float* __restrict__ wd, const float* __restrict__ sg,
    const float* __restrict__ su, const float* __restrict__ sd) {
    __shared__ float sbuf[8192];          // 32 KB, used by both paths
    int bid = blockIdx.x, tid = threadIdx.x;

    if (bid < 1024) {
        // ---- router path ----
        // transpose rw [D][E] -> sbuf [E][D] (rw is 32 KB, L2-resident)
        const float4* rw4 = reinterpret_cast<const float4*>(rw);
        #pragma unroll
        for (int k = 0; k < 8; k++) {
            int i = tid + 256 * k;        // float4 index, 0..2047
            float4 v = rw4[i];
            int d = i >> 1, eb = (i & 1) * 4;
            sbuf[(eb + 0) * 1024 + d] = v.x;
            sbuf[(eb + 1) * 1024 + d] = v.y;
            sbuf[(eb + 2) * 1024 + d] = v.z;
            sbuf[(eb + 3) * 1024 + d] = v.w;
        }
        __syncthreads();

        int t = bid * 8 + (tid >> 5);
        int lid = tid & 31;
        const float4* x4 = reinterpret_cast<const float4*>(x + (size_t)t * DDIM);
        __half* xr16 = g_x16 + (size_t)t * DDIM;
        float acc[NEXP];
        #pragma unroll
        for (int e = 0; e < NEXP; e++) acc[e] = 0.f;
        #pragma unroll
        for (int it = 0; it < 8; it++) {
            int idx = lid + it * 32;
            float4 xv = x4[idx];
            // fused fp16 conversion of x
            __half2 h0 = __floats2half2_rn(xv.x, xv.y);
            __half2 h1 = __floats2half2_rn(xv.z, xv.w);
            *reinterpret_cast<__half2*>(xr16 + 4 * idx)     = h0;
            *reinterpret_cast<__half2*>(xr16 + 4 * idx + 2) = h1;
            #pragma unroll
            for (int e = 0; e < NEXP; e++) {
                float4 w = *reinterpret_cast<const float4*>(&sbuf[e * 1024 + 4 * idx]);
                acc[e] += xv.x * w.x + xv.y * w.y + xv.z * w.z + xv.w * w.w;
            }
        }
        #pragma unroll
        for (int e = 0; e < NEXP; e++) {
            #pragma unroll
            for (int off = 16; off > 0; off >>= 1)
                acc[e] += __shfl_xor_sync(0xffffffffu, acc[e], off);
        }
        if (lid == 0) {
            int i0 = 0;
            #pragma unroll
            for (int e = 1; e < NEXP; e++) if (acc[e] > acc[i0]) i0 = e;
            int i1 = (i0 == 0) ? 1 : 0;
            #pragma unroll
            for (int e = 0; e < NEXP; e++) if (e != i0 && acc[e] > acc[i1]) i1 = e;
            float mx = acc[i0];
            float s = 0.f;
            #pragma unroll
            for (int e = 0; e < NEXP; e++) s += expf(acc[e] - mx);
            float p0 = expf(acc[i0] - mx) / s, p1 = expf(acc[i1] - mx) / s;
            float den = p0 + p1 + 1e-9f;
            float w0 = p0 / den, w1 = p1 / den;
            int q0 = atomicAdd(&g_cnt[i0], 1);
            int q1 = atomicAdd(&g_cnt[i1], 1);
            g_tok[i0 * NTOK + q0] = t;
            g_tok[i1 * NTOK + q1] = t;
            g_slot_e[2 * t] = i0;     g_slot_p[2 * t] = q0;     g_slot_w[2 * t] = w0;
            g_slot_e[2 * t + 1] = i1; g_slot_p[2 * t + 1] = q1; g_slot_w[2 * t + 1] = w1;
        }
    } else {
        // ---- weight transpose path ----
        int b = bid - 1024;
        int z = b >> 10, yy = (b >> 5) & 31, xx = b & 31;
        const float* src; __half* dst;
        if (z < 8)       { src = wg + (size_t)z * MAT;        dst = g_wgT16 + (size_t)z * MAT; }
        else if (z < 16) { src = wu + (size_t)(z - 8) * MAT;  dst = g_wuT16 + (size_t)(z - 8) * MAT; }
        else if (z < 24) { src = wd + (size_t)(z - 16) * MAT; dst = g_wdT16 + (size_t)(z - 16) * MAT; }
        else if (z == 24){ src = sg; dst = g_sgT16; }
        else if (z == 25){ src = su; dst = g_suT16; }
        else             { src = sd; dst = g_sdT16; }
        int bx = xx * 32, by = yy * 32;
        int tx = tid & 31, ty = tid >> 5;
        #pragma unroll
        for (int i = 0; i < 32; i += 8)
            sbuf[(ty + i) * 33 + tx] = src[(size_t)(by + ty + i) * 1024 + bx + tx];
        __syncthreads();
        #pragma unroll
        for (int i = 0; i < 32; i += 8)
            dst[(size_t)(bx + ty + i) * 1024 + by + tx] = __float2half_rn(sbuf[tx * 33 + ty + i]);
    }
}

// ---------------- GEMM1: h = silu(A@Wg) * (A@Wu), fp16 mma -------------------
// CTA 256 thr (4M x 2N warps), tile M=256 N=64, K-chunk 64, warp tile 64x32 dual.
__global__ void __launch_bounds__(256, 1) k_gemm1() {
    int g = blockIdx.z, mt = blockIdx.y, nt = blockIdx.x;
    int cnt = (g == NEXP) ? NTOK : g_cnt[g];
    if (mt * 256 >= cnt) return;

    extern __shared__ __half smh[];
    uint32_t sb = s2u(smh);
    int tid = threadIdx.x, lane = tid & 31, wid = tid >> 5;
    int wm = wid >> 1, wn = wid & 1;
    int lq = lane >> 2, lr = lane & 3;
    int trow = tid >> 3, tcol = (tid & 7) * 8;   // halves

    uint32_t offA[8];
    #pragma unroll
    for (int i = 0; i < 8; i++) {
        int r = mt * 256 + trow + 32 * i;
        int row;
        if (g < NEXP) row = g_tok[g * NTOK + (r < cnt ? r : cnt - 1)];
        else          row = r;
        offA[i] = (uint32_t)row * DDIM + tcol;
    }
    const __half* gb = (g < NEXP) ? g_wgT16 + (size_t)g * MAT : g_sgT16;
    const __half* ub = (g < NEXP) ? g_wuT16 + (size_t)g * MAT : g_suT16;
    uint32_t ncol0 = (uint32_t)nt * 64;

    auto load_stage = [&](int s, int c) {
        uint32_t base = sb + (uint32_t)s * (G1_STAGE_H * 2);
        int k0 = c * KC;
        #pragma unroll
        for (int i = 0; i < 8; i++)
            cp16(base + (uint32_t)((trow + 32 * i) * STRH + tcol) * 2,
                 g_x16 + offA[i] + k0);
        #pragma unroll
        for (int i = 0; i < 2; i++) {
            int r = trow + 32 * i;
            uint32_t d = (uint32_t)(r * STRH + tcol) * 2;
            cp16(base + G1_BG_OFF * 2 + d,
                 gb + (size_t)(ncol0 + r) * DDIM + k0 + tcol);
            cp16(base + G1_BU_OFF * 2 + d,
                 ub + (size_t)(ncol0 + r) * DDIM + k0 + tcol);
        }
    };

    float ag[4][4][4], au[4][4][4];
    #pragma unroll
    for (int mi = 0; mi < 4; mi++)
        #pragma unroll
        for (int ni = 0; ni < 4; ni++)
            #pragma unroll
            for (int q = 0; q < 4; q++) { ag[mi][ni][q] = 0.f; au[mi][ni][q] = 0.f; }

    load_stage(0, 0); CP_COMMIT();
    load_stage(1, 1); CP_COMMIT();
    for (int c = 0; c < NCHUNK; c++) {
        CP_WAIT1();
        __syncthreads();
        if (c + 2 < NCHUNK) load_stage((c + 2) % 3, c + 2);
        CP_COMMIT();
        const __half* As  = smh + (c % 3) * G1_STAGE_H;
        const __half* Bgs = As + G1_BG_OFF;
        const __half* Bus = As + G1_BU_OFF;
        #pragma unroll
        for (int ks = 0; ks < 4; ks++) {
            int kkh = ks * 16 + 2 * lr;
            uint32_t a[4][4];
            #pragma unroll
            for (int mi = 0; mi < 4; mi++) {
                const __half* Ap = As + (wm * 64 + mi * 16 + lq) * STRH + kkh;
                a[mi][0] = ldh2(Ap);
                a[mi][1] = ldh2(Ap + 8 * STRH);
                a[mi][2] = ldh2(Ap + 8);
                a[mi][3] = ldh2(Ap + 8 * STRH + 8);
            }
            #pragma unroll
            for (int ni = 0; ni < 4; ni++) {
                const __half* Bp = Bgs + (wn * 32 + ni * 8 + lq) * STRH + kkh;
                const __half* Up = Bus + (wn * 32 + ni * 8 + lq) * STRH + kkh;
                uint32_t bg0 = ldh2(Bp), bg1 = ldh2(Bp + 8);
                uint32_t bu0 = ldh2(Up), bu1 = ldh2(Up + 8);
                #pragma unroll
                for (int mi = 0; mi < 4; mi++) {
                    MMA16(ag[mi][ni], a[mi], bg0, bg1);
                    MMA16(au[mi][ni], a[mi], bu0, bu1);
                }
            }
        }
    }

    // fused SwiGLU epilogue -> g_h16 (fp16 for GEMM2)
    __half* hp = g_h16 + ((size_t)g * NTOK + mt * 256) * FDIM + nt * 64;
    #pragma unroll
    for (int mi = 0; mi < 4; mi++) {
        int r0 = wm * 64 + mi * 16 + lq;
        #pragma unroll
        for (int ni = 0; ni < 4; ni++) {
            int cc = wn * 32 + ni * 8 + lr * 2;
            float gv, uv, v0, v1;
            gv = ag[mi][ni][0]; uv = au[mi][ni][0];
            v0 = gv / (1.f + __expf(-gv)) * uv;
            gv = ag[mi][ni][1]; uv = au[mi][ni][1];
            v1 = gv / (1.f + __expf(-gv)) * uv;
            *reinterpret_cast<__half2*>(hp + (size_t)r0 * FDIM + cc) = __floats2half2_rn(v0, v1);
            gv = ag[mi][ni][2]; uv = au[mi][ni][2];
            v0 = gv / (1.f + __expf(-gv)) * uv;
            gv = ag[mi][ni][3]; uv = au[mi][ni][3];
            v1 = gv / (1.f + __expf(-gv)) * uv;
            *reinterpret_cast<__half2*>(hp + (size_t)(r0 + 8) * FDIM + cc) = __floats2half2_rn(v0, v1);
        }
    }
}

// ---------------- GEMM2: eo = h @ Wd, fp16 mma, fp16 store --------------------
// CTA 256 thr (4M x 2N), tile M=256 N=128, warp tile 64x64.
__global__ void __launch_bounds__(256, 1) k_gemm2() {
    int g = blockIdx.z, mt = blockIdx.y, nt = blockIdx.x;
    int cnt = (g == NEXP) ? NTOK : g_cnt[g];
    if (mt * 256 >= cnt) return;

    extern __shared__ __half smh[];
    uint32_t sb = s2u(smh);
    int tid = threadIdx.x, lane = tid & 31, wid = tid >> 5;
    int wm = wid >> 1, wn = wid & 1;
    int lq = lane >> 2, lr = lane & 3;
    int trow = tid >> 3, tcol = (tid & 7) * 8;

    const __half* abase = g_h16 + ((size_t)g * NTOK + mt * 256) * FDIM;
    const __half* bbase = (g < NEXP) ? g_wdT16 + (size_t)g * MAT : g_sdT16;
    uint32_t ncol0 = (uint32_t)nt * 128;

    auto load_stage = [&](int s, int c) {
        uint32_t base = sb + (uint32_t)s * (G2_STAGE_H * 2);
        int k0 = c * KC;
        #pragma unroll
        for (int i = 0; i < 8; i++) {
            int r = trow + 32 * i;
            cp16(base + (uint32_t)(r * STRH + tcol) * 2,
                 abase + (size_t)r * FDIM + k0 + tcol);
        }
        #pragma unroll
        for (int i = 0; i < 4; i++) {
            int r = trow + 32 * i;
            cp16(base + G2_B_OFF * 2 + (uint32_t)(r * STRH + tcol) * 2,
                 bbase + (size_t)(ncol0 + r) * FDIM + k0 + tcol);
        }
    };

    float ac[4][8][4];
    #pragma unroll
    for (int mi = 0; mi < 4; mi++)
        #pragma unroll
        for (int ni = 0; ni < 8; ni++)
            #pragma unroll
            for (int q = 0; q < 4; q++) ac[mi][ni][q] = 0.f;

    load_stage(0, 0); CP_COMMIT();
    load_stage(1, 1); CP_COMMIT();
    for (int c = 0; c < NCHUNK; c++) {
        CP_WAIT1();
        __syncthreads();
        if (c + 2 < NCHUNK) load_stage((c + 2) % 3, c + 2);
        CP_COMMIT();
        const __half* As = smh + (c % 3) * G2_STAGE_H;
        const __half* Bs = As + G2_B_OFF;
        #pragma unroll
        for (int ks = 0; ks < 4; ks++) {
            int kkh = ks * 16 + 2 * lr;
            uint32_t a[4][4];
            #pragma unroll
            for (int mi = 0; mi < 4; mi++) {
                const __half* Ap = As + (wm * 64 + mi * 16 + lq) * STRH + kkh;
                a[mi][0] = ldh2(Ap);
                a[mi][1] = ldh2(Ap + 8 * STRH);
                a[mi][2] = ldh2(Ap + 8);
                a[mi][3] = ldh2(Ap + 8 * STRH + 8);
            }
            #pragma unroll
            for (int ni = 0; ni < 8; ni++) {
                const __half* Bp = Bs + (wn * 64 + ni * 8 + lq) * STRH + kkh;
                uint32_t b0 = ldh2(Bp), b1 = ldh2(Bp + 8);
                #pragma unroll
                for (int mi = 0; mi < 4; mi++) MMA16(ac[mi][ni], a[mi], b0, b1);
            }
        }
    }

    __half* ep = g_eoh + ((size_t)g * NTOK + mt * 256) * DDIM + nt * 128;
    #pragma unroll
    for (int mi = 0; mi < 4; mi++) {
        int r0 = wm * 64 + mi * 16 + lq;
        #pragma unroll
        for (int ni = 0; ni < 8; ni++) {
            int cc = wn * 64 + ni * 8 + lr * 2;
            *reinterpret_cast<__half2*>(ep + (size_t)r0 * DDIM + cc) =
                __floats2half2_rn(ac[mi][ni][0], ac[mi][ni][1]);
            *reinterpret_cast<__half2*>(ep + (size_t)(r0 + 8) * DDIM + cc) =
                __floats2half2_rn(ac[mi][ni][2], ac[mi][ni][3]);
        }
    }
}

// ---------------- combine: out = shared + w0*eo0 + w1*eo1 --------------------
__global__ void k_combine(float* __restrict__ out) {
    int t = blockIdx.x;
    int e0 = g_slot_e[2 * t], e1 = g_slot_e[2 * t + 1];
    int p0 = g_slot_p[2 * t], p1 = g_slot_p[2 * t + 1];
    float w0 = g_slot_w[2 * t], w1 = g_slot_w[2 * t + 1];
    const __half2* sh = reinterpret_cast<const __half2*>(g_eoh + ((size_t)NEXP * NTOK + t) * DDIM);
    const __half2* a  = reinterpret_cast<const __half2*>(g_eoh + ((size_t)e0 * NTOK + p0) * DDIM);
    const __half2* b  = reinterpret_cast<const __half2*>(g_eoh + ((size_t)e1 * NTOK + p1) * DDIM);
    float4* o = reinterpret_cast<float4*>(out + (size_t)t * DDIM);
    int i = threadIdx.x;      // 256 threads * 4 floats = 1024
    float2 s0 = __half22float2(sh[2 * i]),  s1 = __half22float2(sh[2 * i + 1]);
    float2 a0 = __half22float2(a[2 * i]),   a1 = __half22float2(a[2 * i + 1]);
    float2 b0 = __half22float2(b[2 * i]),   b1 = __half22float2(b[2 * i + 1]);
    o[i] = make_float4(s0.x + w0 * a0.x + w1 * b0.x,
                       s0.y + w0 * a0.y + w1 * b0.y,
                       s1.x + w0 * a1.x + w1 * b1.x,
                       s1.y + w0 * a1.y + w1 * b1.y);
}

// ---------------- launch -----------------------------------------------------
extern "C" void kernel_launch(void* const* d_in, const int* in_sizes, int n_in,
                              void* d_out, int out_size) {
    const float* x  = (const float*)d_in[0];
    const float* rw = (const float*)d_in[1];
    const float* sg = (const float*)d_in[2];
    const float* su = (const float*)d_in[3];
    const float* sd = (const float*)d_in[4];
    const float* wg = (const float*)d_in[5];
    const float* wu = (const float*)d_in[6];
    const float* wd = (const float*)d_in[7];
    float* out = (float*)d_out;

    cudaFuncSetAttribute(k_gemm1, cudaFuncAttributeMaxDynamicSharedMemorySize, G1_SMEM);
    cudaFuncSetAttribute(k_gemm2, cudaFuncAttributeMaxDynamicSharedMemorySize, G2_SMEM);

    void* cntp = nullptr;
    cudaGetSymbolAddress(&cntp, g_cnt);
    cudaMemsetAsync(cntp, 0, NEXP * sizeof(int));

    k_pre<<<1024 + 27 * 1024, 256>>>(x, rw, wg, wu, wd, sg, su, sd);
    k_gemm1<<<dim3(16, 32, NGRP), 256, G1_SMEM>>>();
    k_gemm2<<<dim3(8, 32, NGRP), 256, G2_SMEM>>>();
    k_combine<<<NTOK, 256>>>(out);
}